// round 1
// baseline (speedup 1.0000x reference)
#include <cuda_runtime.h>
#include <math.h>

#define B_ 32
#define L_ 2048
#define D_ 1024

// Scratch (no cudaMalloc allowed): ~2.3 MB total
__device__ float g_ht[B_ * D_];            // 128 KB
__device__ float g_spart[B_ * L_ * 8];     // 2 MB  (per-k-block score partials)
__device__ float g_wpart[B_ * 8 * D_];     // 1 MB  (per-l-chunk weighted partials)

// ---------------------------------------------------------------------------
// ht_proj[b,k] = sum_d x[b,d] * Wa[k,d]   (Wa row stride = 2D, t-half)
// one warp per output element
// ---------------------------------------------------------------------------
__global__ void ht_kernel(const float* __restrict__ x, const float* __restrict__ Wa) {
    int gw   = (blockIdx.x * blockDim.x + threadIdx.x) >> 5;
    int lane = threadIdx.x & 31;
    if (gw >= B_ * D_) return;
    int b = gw >> 10;
    int k = gw & (D_ - 1);
    const float* xr = x + (size_t)b * D_;
    const float* wr = Wa + (size_t)k * (2 * D_);
    float s = 0.f;
    #pragma unroll
    for (int d = lane * 4; d < D_; d += 32 * 4) {
        float4 xv = *(const float4*)(xr + d);
        float4 wv = *(const float4*)(wr + d);
        s += xv.x * wv.x + xv.y * wv.y + xv.z * wv.z + xv.w * wv.w;
    }
    #pragma unroll
    for (int o = 16; o; o >>= 1) s += __shfl_down_sync(0xFFFFFFFFu, s, o);
    if (lane == 0) g_ht[gw] = s;
}

// ---------------------------------------------------------------------------
// Fused main GEMM + tanh + Va-dot:
//   hs[row,k] = sum_d ctx[row,d] * Wa[k, D+d]     (row = b*L + l)
//   spart[row, kb] = sum_{k in block kb} tanh(ht[b,k] + hs[row,k]) * Va[k]
// 128x128 tile, BK=16, 8x8 per-thread micro-tile, 256 threads
// ---------------------------------------------------------------------------
#define BM 128
#define BN 128
#define BK 16
#define TM 8
#define TN 8

__global__ __launch_bounds__(256) void gemm_score_kernel(
    const float* __restrict__ ctx, const float* __restrict__ Wa,
    const float* __restrict__ Va)
{
    __shared__ float As[BK][BM + 4];
    __shared__ float Bs[BK][BN + 4];
    __shared__ float red[BM][16];

    const int tid = threadIdx.x;
    const int tx  = tid & 15;
    const int ty  = tid >> 4;
    const int rowBase = blockIdx.y * BM;      // into 65536 rows
    const int colBase = blockIdx.x * BN;      // into 1024 k
    const int b = blockIdx.y >> 4;            // 2048 rows (16 blocks) per batch

    float acc[TM][TN];
    #pragma unroll
    for (int i = 0; i < TM; i++)
        #pragma unroll
        for (int j = 0; j < TN; j++) acc[i][j] = 0.f;

    const float* actx = ctx + (size_t)rowBase * D_;
    const float* bwa  = Wa  + (size_t)colBase * (2 * D_) + D_;   // s-half

    for (int dk = 0; dk < D_; dk += BK) {
        #pragma unroll
        for (int i = 0; i < 2; i++) {
            int v = tid + i * 256;           // 512 float4 per tile
            int r = v >> 2;                  // 0..127
            int c = (v & 3) * 4;             // 0,4,8,12
            float4 a = *(const float4*)(actx + (size_t)r * D_ + dk + c);
            As[c + 0][r] = a.x; As[c + 1][r] = a.y;
            As[c + 2][r] = a.z; As[c + 3][r] = a.w;
            float4 w = *(const float4*)(bwa + (size_t)r * (2 * D_) + dk + c);
            Bs[c + 0][r] = w.x; Bs[c + 1][r] = w.y;
            Bs[c + 2][r] = w.z; Bs[c + 3][r] = w.w;
        }
        __syncthreads();
        #pragma unroll
        for (int kk = 0; kk < BK; kk++) {
            float ra[TM], rb[TN];
            *(float4*)&ra[0] = *(const float4*)&As[kk][ty * TM];
            *(float4*)&ra[4] = *(const float4*)&As[kk][ty * TM + 4];
            *(float4*)&rb[0] = *(const float4*)&Bs[kk][tx * TN];
            *(float4*)&rb[4] = *(const float4*)&Bs[kk][tx * TN + 4];
            #pragma unroll
            for (int i = 0; i < TM; i++)
                #pragma unroll
                for (int j = 0; j < TN; j++)
                    acc[i][j] += ra[i] * rb[j];
        }
        __syncthreads();
    }

    // Epilogue: tanh + Va-weighted reduce over this block's 128 k's
    float htv[TN], vav[TN];
    #pragma unroll
    for (int j = 0; j < TN; j++) {
        int k = colBase + tx * TN + j;
        htv[j] = g_ht[b * D_ + k];
        vav[j] = Va[k];
    }
    #pragma unroll
    for (int i = 0; i < TM; i++) {
        float s = 0.f;
        #pragma unroll
        for (int j = 0; j < TN; j++)
            s += tanhf(acc[i][j] + htv[j]) * vav[j];
        red[ty * TM + i][tx] = s;
    }
    __syncthreads();
    if (tid < BM) {
        float s = 0.f;
        #pragma unroll
        for (int t = 0; t < 16; t++) s += red[tid][t];
        g_spart[(size_t)(rowBase + tid) * 8 + blockIdx.x] = s;
    }
}

// ---------------------------------------------------------------------------
// softmax over L=2048 per batch; one block per b; writes attn output
// ---------------------------------------------------------------------------
__global__ void softmax_kernel(float* __restrict__ out_attn) {
    int b   = blockIdx.x;
    int tid = threadIdx.x;      // 256
    __shared__ float sm[256];
    float local[8];
    float mx = -1e30f;
    #pragma unroll
    for (int i = 0; i < 8; i++) {
        int l = tid + i * 256;
        const float* p = g_spart + ((size_t)b * L_ + l) * 8;
        float s = 0.f;
        #pragma unroll
        for (int t = 0; t < 8; t++) s += p[t];
        local[i] = s;
        mx = fmaxf(mx, s);
    }
    sm[tid] = mx; __syncthreads();
    for (int o = 128; o; o >>= 1) {
        if (tid < o) sm[tid] = fmaxf(sm[tid], sm[tid + o]);
        __syncthreads();
    }
    mx = sm[0]; __syncthreads();
    float sum = 0.f;
    #pragma unroll
    for (int i = 0; i < 8; i++) { local[i] = expf(local[i] - mx); sum += local[i]; }
    sm[tid] = sum; __syncthreads();
    for (int o = 128; o; o >>= 1) {
        if (tid < o) sm[tid] += sm[tid + o];
        __syncthreads();
    }
    float inv = 1.f / sm[0];
    #pragma unroll
    for (int i = 0; i < 8; i++)
        out_attn[(size_t)b * L_ + tid + i * 256] = local[i] * inv;
}

// ---------------------------------------------------------------------------
// weighted[b,d] = sum_l attn[b,l] * ctx[b,l,d]  — split over 8 l-chunks
// ---------------------------------------------------------------------------
__global__ void weighted_part_kernel(const float* __restrict__ ctx,
                                     const float* __restrict__ attn) {
    int b  = blockIdx.y;
    int lc = blockIdx.x;            // 8 chunks of 256 l
    int d  = threadIdx.x;           // 1024
    __shared__ float sa[256];
    if (threadIdx.x < 256)
        sa[threadIdx.x] = attn[(size_t)b * L_ + lc * 256 + threadIdx.x];
    __syncthreads();
    const float* cb = ctx + ((size_t)b * L_ + (size_t)lc * 256) * D_ + d;
    float a0 = 0.f, a1 = 0.f, a2 = 0.f, a3 = 0.f;
    for (int l = 0; l < 256; l += 4) {
        a0 += sa[l + 0] * cb[(size_t)(l + 0) * D_];
        a1 += sa[l + 1] * cb[(size_t)(l + 1) * D_];
        a2 += sa[l + 2] * cb[(size_t)(l + 2) * D_];
        a3 += sa[l + 3] * cb[(size_t)(l + 3) * D_];
    }
    g_wpart[((size_t)b * 8 + lc) * D_ + d] = (a0 + a1) + (a2 + a3);
}

__global__ void weighted_reduce_kernel(float* __restrict__ out_w) {
    int i = blockIdx.x * blockDim.x + threadIdx.x;
    if (i >= B_ * D_) return;
    int b = i >> 10, d = i & (D_ - 1);
    float s = 0.f;
    #pragma unroll
    for (int lc = 0; lc < 8; lc++)
        s += g_wpart[((size_t)b * 8 + lc) * D_ + d];
    out_w[i] = s;
}

// ---------------------------------------------------------------------------
extern "C" void kernel_launch(void* const* d_in, const int* in_sizes, int n_in,
                              void* d_out, int out_size) {
    const float* x   = (const float*)d_in[0];   // (32,1024)
    const float* ctx = (const float*)d_in[1];   // (32,2048,1024)
    const float* Wa  = (const float*)d_in[2];   // (1024,2048)
    const float* Va  = (const float*)d_in[3];   // (1,1024)
    float* out      = (float*)d_out;
    float* out_w    = out;                       // (32,1024)
    float* out_attn = out + B_ * D_;             // (32,2048)

    ht_kernel<<<(B_ * D_) / 8, 256>>>(x, Wa);
    gemm_score_kernel<<<dim3(D_ / BN, (B_ * L_) / BM), 256>>>(ctx, Wa, Va);
    softmax_kernel<<<B_, 256>>>(out_attn);
    weighted_part_kernel<<<dim3(8, B_), 1024>>>(ctx, out_attn);
    weighted_reduce_kernel<<<(B_ * D_ + 255) / 256, 256>>>(out_w);
}

// round 4
// speedup vs baseline: 2.7677x; 2.7677x over previous
#include <cuda_runtime.h>
#include <cstdint>
#include <math.h>

#define B_ 32
#define L_ 2048
#define D_ 1024

#define BM 128
#define BN 128
#define BK 32
#define NCB (D_ / BN)            // 8 col blocks (k-dim)
#define NRB ((B_ * L_) / BM)     // 512 row blocks
#define NITER (D_ / BK)          // 32 mainloop iterations

// Scratch (no cudaMalloc allowed)
__device__ float g_ht[B_ * D_];              // 128 KB
__device__ float g_spart[B_ * L_ * NCB];     // 2 MB
__device__ float g_wpart[B_ * 8 * D_];       // 1 MB

// ---------------------------------------------------------------------------
__device__ __forceinline__ uint32_t smem_u32(const void* p) {
    uint32_t a;
    asm("{ .reg .u64 t; cvta.to.shared.u64 t, %1; cvt.u32.u64 %0, t; }"
        : "=r"(a) : "l"(p));
    return a;
}

__device__ __forceinline__ void cp16(uint32_t s, const void* g) {
    asm volatile("cp.async.cg.shared.global [%0], [%1], 16;"
                 :: "r"(s), "l"(g) : "memory");
}
#define CP_COMMIT() asm volatile("cp.async.commit_group;" ::: "memory")
#define CP_WAIT1()  asm volatile("cp.async.wait_group 1;" ::: "memory")

__device__ __forceinline__ void mma_tf32(float* c, const uint32_t* a,
                                         const uint32_t* b) {
    asm volatile(
        "mma.sync.aligned.m16n8k8.row.col.f32.tf32.tf32.f32 "
        "{%0,%1,%2,%3}, {%4,%5,%6,%7}, {%8,%9}, {%0,%1,%2,%3};"
        : "+f"(c[0]), "+f"(c[1]), "+f"(c[2]), "+f"(c[3])
        : "r"(a[0]), "r"(a[1]), "r"(a[2]), "r"(a[3]), "r"(b[0]), "r"(b[1]));
}

// FMA-only tanh (rational 13/6 + bit-hack Newton reciprocal). No MUFU.
__device__ __forceinline__ float tanh_fma(float x) {
    const float a1 = 4.89352455891786e-03f, a3 = 6.37261928875436e-04f,
                a5 = 1.48572235717979e-05f, a7 = 5.12229709037114e-08f,
                a9 = -8.60467152213735e-11f, a11 = 2.00018790482477e-13f,
                a13 = -2.76076847742355e-16f;
    const float b0 = 4.89352518554385e-03f, b2 = 2.26843463243900e-03f,
                b4 = 1.18534705686654e-04f, b6 = 1.19825839466702e-06f;
    x = fminf(fmaxf(x, -7.90531110763549805f), 7.90531110763549805f);
    float x2 = x * x;
    float p = fmaf(x2, a13, a11);
    p = fmaf(x2, p, a9);
    p = fmaf(x2, p, a7);
    p = fmaf(x2, p, a5);
    p = fmaf(x2, p, a3);
    p = fmaf(x2, p, a1);
    p = p * x;
    float q = fmaf(x2, b6, b4);
    q = fmaf(x2, q, b2);
    q = fmaf(x2, q, b0);
    float r = __int_as_float(0x7EF311C3 - __float_as_int(q));
    r = r * fmaf(-q, r, 2.0f);
    r = r * fmaf(-q, r, 2.0f);
    r = r * fmaf(-q, r, 2.0f);
    return p * r;
}

// ---------------------------------------------------------------------------
// ht_proj[b,k] = sum_d x[b,d] * Wa[k,d]  (t-half), full fp32
// ---------------------------------------------------------------------------
__global__ void ht_kernel(const float* __restrict__ x, const float* __restrict__ Wa) {
    int gw   = (blockIdx.x * blockDim.x + threadIdx.x) >> 5;
    int lane = threadIdx.x & 31;
    if (gw >= B_ * D_) return;
    int b = gw >> 10;
    int k = gw & (D_ - 1);
    const float* xr = x + (size_t)b * D_;
    const float* wr = Wa + (size_t)k * (2 * D_);
    float s = 0.f;
    #pragma unroll
    for (int d = lane * 4; d < D_; d += 32 * 4) {
        float4 xv = *(const float4*)(xr + d);
        float4 wv = *(const float4*)(wr + d);
        s += xv.x * wv.x + xv.y * wv.y + xv.z * wv.z + xv.w * wv.w;
    }
    #pragma unroll
    for (int o = 16; o; o >>= 1) s += __shfl_down_sync(0xFFFFFFFFu, s, o);
    if (lane == 0) g_ht[gw] = s;
}

// ---------------------------------------------------------------------------
// mma.sync tf32 fused GEMM + tanh + Va-dot
// smem layout (bytes):
//   A0: 0       (128 rows x 36 words = 18432)
//   B0: 18432
//   A1: 36864
//   B1: 55296
//   HT: 73728 (512), VA: 74240 (512), RED: 74752 (2048)  -> total 76800
// ---------------------------------------------------------------------------
#define ROWW 36                  // padded row stride in words
#define SM_A0 0
#define SM_B0 18432
#define SM_A1 36864
#define SM_B1 55296
#define SM_HT 73728
#define SM_VA 74240
#define SM_RED 74752
#define SMEM_TOTAL 76800

__device__ __forceinline__ void load_tile(uint32_t sA, uint32_t sB,
    const float* __restrict__ Ag, const float* __restrict__ Bg,
    int dk, int tid)
{
    #pragma unroll
    for (int i = 0; i < 4; i++) {
        int ch = tid + i * 256;            // 0..1023
        int row = ch >> 3;
        int cc  = ch & 7;
        cp16(sA + row * (ROWW * 4) + cc * 16,
             Ag + (size_t)row * D_ + dk + cc * 4);
        cp16(sB + row * (ROWW * 4) + cc * 16,
             Bg + (size_t)row * (2 * D_) + dk + cc * 4);
    }
}

__global__ __launch_bounds__(256, 1) void gemm_score_mma(
    const float* __restrict__ ctx, const float* __restrict__ Wa,
    const float* __restrict__ Va)
{
    extern __shared__ char smem[];
    const uint32_t sbase = smem_u32(smem);
    const int tid  = threadIdx.x;
    const int w    = tid >> 5;
    const int lane = tid & 31;
    const int g    = lane >> 2;            // group id (row within 8)
    const int t    = lane & 3;             // thread in group (col within 4)
    const int warpM = (w >> 2) * 64;
    const int warpN = (w & 3) * 32;
    const int colBase = blockIdx.x * BN;
    const int rowBase = blockIdx.y * BM;
    const int b = rowBase >> 11;           // 2048 rows per batch

    float* ht_s = (float*)(smem + SM_HT);
    float* va_s = (float*)(smem + SM_VA);
    float* red  = (float*)(smem + SM_RED);
    if (tid < 128) ht_s[tid] = g_ht[b * D_ + colBase + tid];
    else           va_s[tid - 128] = Va[colBase + tid - 128];

    const float* Ag = ctx + (size_t)rowBase * D_;
    const float* Bg = Wa + (size_t)colBase * (2 * D_) + D_;   // s-half

    float c[4][4][4];
    #pragma unroll
    for (int i = 0; i < 4; i++)
        #pragma unroll
        for (int j = 0; j < 4; j++)
            #pragma unroll
            for (int r = 0; r < 4; r++) c[i][j][r] = 0.f;

    load_tile(sbase + SM_A0, sbase + SM_B0, Ag, Bg, 0, tid);
    CP_COMMIT();
    load_tile(sbase + SM_A1, sbase + SM_B1, Ag, Bg, BK, tid);
    CP_COMMIT();

    const int aw0 = (warpM + g) * ROWW + t;   // per-thread A base word
    const int bw0 = (warpN + g) * ROWW + t;   // per-thread B base word

    for (int it = 0; it < NITER; it++) {
        CP_WAIT1();
        __syncthreads();
        const uint32_t* As = (const uint32_t*)(smem + ((it & 1) ? SM_A1 : SM_A0));
        const uint32_t* Bs = (const uint32_t*)(smem + ((it & 1) ? SM_B1 : SM_B0));

        #pragma unroll
        for (int k8 = 0; k8 < 4; k8++) {
            uint32_t a[4][4], bfrag[4][2];
            #pragma unroll
            for (int i = 0; i < 4; i++) {
                int wdx = aw0 + i * (16 * ROWW) + k8 * 8;
                a[i][0] = As[wdx];
                a[i][1] = As[wdx + 8 * ROWW];
                a[i][2] = As[wdx + 4];
                a[i][3] = As[wdx + 8 * ROWW + 4];
            }
            #pragma unroll
            for (int j = 0; j < 4; j++) {
                int wdx = bw0 + j * (8 * ROWW) + k8 * 8;
                bfrag[j][0] = Bs[wdx];
                bfrag[j][1] = Bs[wdx + 4];
            }
            #pragma unroll
            for (int i = 0; i < 4; i++)
                #pragma unroll
                for (int j = 0; j < 4; j++)
                    mma_tf32(c[i][j], a[i], bfrag[j]);
        }
        __syncthreads();
        if (it + 2 < NITER)
            load_tile(sbase + ((it & 1) ? SM_A1 : SM_A0),
                      sbase + ((it & 1) ? SM_B1 : SM_B0),
                      Ag, Bg, (it + 2) * BK, tid);
        CP_COMMIT();
    }

    // Epilogue: tanh(c + ht) * Va, reduce over 128 cols of this k-block
    #pragma unroll
    for (int i = 0; i < 4; i++) {
        float s0 = 0.f, s1 = 0.f;
        #pragma unroll
        for (int j = 0; j < 4; j++) {
            int c0 = warpN + j * 8 + 2 * t;
            float h0 = ht_s[c0], h1 = ht_s[c0 + 1];
            float v0 = va_s[c0], v1 = va_s[c0 + 1];
            s0 += tanh_fma(c[i][j][0] + h0) * v0;
            s0 += tanh_fma(c[i][j][1] + h1) * v1;
            s1 += tanh_fma(c[i][j][2] + h0) * v0;
            s1 += tanh_fma(c[i][j][3] + h1) * v1;
        }
        s0 += __shfl_xor_sync(0xFFFFFFFFu, s0, 1);
        s0 += __shfl_xor_sync(0xFFFFFFFFu, s0, 2);
        s1 += __shfl_xor_sync(0xFFFFFFFFu, s1, 1);
        s1 += __shfl_xor_sync(0xFFFFFFFFu, s1, 2);
        if (t == 0) {
            red[(warpM + i * 16 + g) * 4 + (w & 3)] = s0;
            red[(warpM + i * 16 + 8 + g) * 4 + (w & 3)] = s1;
        }
    }
    __syncthreads();
    if (tid < 128) {
        float s = red[tid * 4] + red[tid * 4 + 1] + red[tid * 4 + 2] + red[tid * 4 + 3];
        g_spart[(size_t)(rowBase + tid) * NCB + blockIdx.x] = s;
    }
}

// ---------------------------------------------------------------------------
// softmax over L=2048 per batch
// ---------------------------------------------------------------------------
__global__ void softmax_kernel(float* __restrict__ out_attn) {
    int b   = blockIdx.x;
    int tid = threadIdx.x;      // 256
    __shared__ float sm[256];
    float local[8];
    float mx = -1e30f;
    #pragma unroll
    for (int i = 0; i < 8; i++) {
        int l = tid + i * 256;
        const float* p = g_spart + ((size_t)b * L_ + l) * NCB;
        float s = 0.f;
        #pragma unroll
        for (int q = 0; q < NCB; q++) s += p[q];
        local[i] = s;
        mx = fmaxf(mx, s);
    }
    sm[tid] = mx; __syncthreads();
    for (int o = 128; o; o >>= 1) {
        if (tid < o) sm[tid] = fmaxf(sm[tid], sm[tid + o]);
        __syncthreads();
    }
    mx = sm[0]; __syncthreads();
    float sum = 0.f;
    #pragma unroll
    for (int i = 0; i < 8; i++) { local[i] = expf(local[i] - mx); sum += local[i]; }
    sm[tid] = sum; __syncthreads();
    for (int o = 128; o; o >>= 1) {
        if (tid < o) sm[tid] += sm[tid + o];
        __syncthreads();
    }
    float inv = 1.f / sm[0];
    #pragma unroll
    for (int i = 0; i < 8; i++)
        out_attn[(size_t)b * L_ + tid + i * 256] = local[i] * inv;
}

// ---------------------------------------------------------------------------
// weighted[b,d] = sum_l attn[b,l] * ctx[b,l,d]
// ---------------------------------------------------------------------------
__global__ void weighted_part_kernel(const float* __restrict__ ctx,
                                     const float* __restrict__ attn) {
    int b  = blockIdx.y;
    int lc = blockIdx.x;
    int d  = threadIdx.x;
    __shared__ float sa[256];
    if (threadIdx.x < 256)
        sa[threadIdx.x] = attn[(size_t)b * L_ + lc * 256 + threadIdx.x];
    __syncthreads();
    const float* cb = ctx + ((size_t)b * L_ + (size_t)lc * 256) * D_ + d;
    float a0 = 0.f, a1 = 0.f, a2 = 0.f, a3 = 0.f;
    for (int l = 0; l < 256; l += 4) {
        a0 += sa[l + 0] * cb[(size_t)(l + 0) * D_];
        a1 += sa[l + 1] * cb[(size_t)(l + 1) * D_];
        a2 += sa[l + 2] * cb[(size_t)(l + 2) * D_];
        a3 += sa[l + 3] * cb[(size_t)(l + 3) * D_];
    }
    g_wpart[((size_t)b * 8 + lc) * D_ + d] = (a0 + a1) + (a2 + a3);
}

__global__ void weighted_reduce_kernel(float* __restrict__ out_w) {
    int i = blockIdx.x * blockDim.x + threadIdx.x;
    if (i >= B_ * D_) return;
    int b = i >> 10, d = i & (D_ - 1);
    float s = 0.f;
    #pragma unroll
    for (int lc = 0; lc < 8; lc++)
        s += g_wpart[((size_t)b * 8 + lc) * D_ + d];
    out_w[i] = s;
}

// ---------------------------------------------------------------------------
extern "C" void kernel_launch(void* const* d_in, const int* in_sizes, int n_in,
                              void* d_out, int out_size) {
    const float* x   = (const float*)d_in[0];   // (32,1024)
    const float* ctx = (const float*)d_in[1];   // (32,2048,1024)
    const float* Wa  = (const float*)d_in[2];   // (1024,2048)
    const float* Va  = (const float*)d_in[3];   // (1,1024)
    float* out      = (float*)d_out;
    float* out_w    = out;                       // (32,1024)
    float* out_attn = out + B_ * D_;             // (32,2048)

    cudaFuncSetAttribute(gemm_score_mma,
                         cudaFuncAttributeMaxDynamicSharedMemorySize, SMEM_TOTAL);

    ht_kernel<<<(B_ * D_) / 8, 256>>>(x, Wa);
    gemm_score_mma<<<dim3(NCB, NRB), 256, SMEM_TOTAL>>>(ctx, Wa, Va);
    softmax_kernel<<<B_, 256>>>(out_attn);
    weighted_part_kernel<<<dim3(8, B_), 1024>>>(ctx, out_attn);
    weighted_reduce_kernel<<<(B_ * D_ + 255) / 256, 256>>>(out_w);
}

// round 7
// speedup vs baseline: 3.5649x; 1.2881x over previous
#include <cuda_runtime.h>
#include <cstdint>
#include <math.h>

#define B_ 32
#define L_ 2048
#define D_ 1024

#define BM 128
#define BN 128
#define BK 16
#define NCB (D_ / BN)            // 8 col blocks (k-dim)
#define NRB ((B_ * L_) / BM)     // 512 row blocks
#define NITER (D_ / BK)          // 64 mainloop iterations
#define NSTAGE 4

// Scratch (no cudaMalloc allowed)
__device__ float g_ht[B_ * D_];              // 128 KB
__device__ float g_spart[B_ * L_ * NCB];     // 2 MB
__device__ float g_wpart[B_ * 8 * D_];       // 1 MB

// ---------------------------------------------------------------------------
__device__ __forceinline__ uint32_t smem_u32(const void* p) {
    uint32_t a;
    asm("{ .reg .u64 t; cvta.to.shared.u64 t, %1; cvt.u32.u64 %0, t; }"
        : "=r"(a) : "l"(p));
    return a;
}

__device__ __forceinline__ void cp16(uint32_t s, const void* g) {
    asm volatile("cp.async.cg.shared.global [%0], [%1], 16;"
                 :: "r"(s), "l"(g) : "memory");
}
#define CP_COMMIT() asm volatile("cp.async.commit_group;" ::: "memory")
#define CP_WAIT2()  asm volatile("cp.async.wait_group 2;" ::: "memory")

__device__ __forceinline__ void mma_tf32(float* c, const uint32_t* a,
                                         const uint32_t* b) {
    asm volatile(
        "mma.sync.aligned.m16n8k8.row.col.f32.tf32.tf32.f32 "
        "{%0,%1,%2,%3}, {%4,%5,%6,%7}, {%8,%9}, {%0,%1,%2,%3};"
        : "+f"(c[0]), "+f"(c[1]), "+f"(c[2]), "+f"(c[3])
        : "r"(a[0]), "r"(a[1]), "r"(a[2]), "r"(a[3]), "r"(b[0]), "r"(b[1]));
}

// swizzled word index within a 128x16-word (64B-row) tile:
//   logical (row, word w) with w = chunk*4 + t  ->  row*16 + (chunk^((row>>1)&3))*4 + t
__device__ __forceinline__ int sw_word(int row, int chunk, int t) {
    return row * 16 + ((chunk ^ ((row >> 1) & 3)) << 2) + t;
}

// FMA-only tanh (rational 13/6 + bit-hack Newton reciprocal). No MUFU.
__device__ __forceinline__ float tanh_fma(float x) {
    const float a1 = 4.89352455891786e-03f, a3 = 6.37261928875436e-04f,
                a5 = 1.48572235717979e-05f, a7 = 5.12229709037114e-08f,
                a9 = -8.60467152213735e-11f, a11 = 2.00018790482477e-13f,
                a13 = -2.76076847742355e-16f;
    const float b0 = 4.89352518554385e-03f, b2 = 2.26843463243900e-03f,
                b4 = 1.18534705686654e-04f, b6 = 1.19825839466702e-06f;
    x = fminf(fmaxf(x, -7.90531110763549805f), 7.90531110763549805f);
    float x2 = x * x;
    float p = fmaf(x2, a13, a11);
    p = fmaf(x2, p, a9);
    p = fmaf(x2, p, a7);
    p = fmaf(x2, p, a5);
    p = fmaf(x2, p, a3);
    p = fmaf(x2, p, a1);
    p = p * x;
    float q = fmaf(x2, b6, b4);
    q = fmaf(x2, q, b2);
    q = fmaf(x2, q, b0);
    float r = __int_as_float(0x7EF311C3 - __float_as_int(q));
    r = r * fmaf(-q, r, 2.0f);
    r = r * fmaf(-q, r, 2.0f);
    r = r * fmaf(-q, r, 2.0f);
    return p * r;
}

// ---------------------------------------------------------------------------
// ht_proj[b,k] = sum_d x[b,d] * Wa[k,d]  (t-half), full fp32
// ---------------------------------------------------------------------------
__global__ void ht_kernel(const float* __restrict__ x, const float* __restrict__ Wa) {
    int gw   = (blockIdx.x * blockDim.x + threadIdx.x) >> 5;
    int lane = threadIdx.x & 31;
    if (gw >= B_ * D_) return;
    int b = gw >> 10;
    int k = gw & (D_ - 1);
    const float* xr = x + (size_t)b * D_;
    const float* wr = Wa + (size_t)k * (2 * D_);
    float s = 0.f;
    #pragma unroll
    for (int d = lane * 4; d < D_; d += 32 * 4) {
        float4 xv = *(const float4*)(xr + d);
        float4 wv = *(const float4*)(wr + d);
        s += xv.x * wv.x + xv.y * wv.y + xv.z * wv.z + xv.w * wv.w;
    }
    #pragma unroll
    for (int o = 16; o; o >>= 1) s += __shfl_down_sync(0xFFFFFFFFu, s, o);
    if (lane == 0) g_ht[gw] = s;
}

// ---------------------------------------------------------------------------
// mma.sync tf32 fused GEMM + tanh + Va-dot
// smem (bytes): 4 stages x (A 8KB + B 8KB) = 65536
//   HT: 65536 (512), VA: 66048 (512), RED: 66560 (2048) -> 68608 total
// ---------------------------------------------------------------------------
#define STG(s)  ((s) * 16384)
#define STG_B   8192
#define SM_HT   65536
#define SM_VA   66048
#define SM_RED  66560
#define SMEM_TOTAL 68608

__device__ __forceinline__ void load_tile(uint32_t sA, uint32_t sB,
    const float* __restrict__ Ag, const float* __restrict__ Bg,
    int dk, int tid)
{
    #pragma unroll
    for (int i = 0; i < 2; i++) {
        int ch  = tid + i * 256;           // 0..511
        int row = ch >> 2;                 // 0..127
        int cc  = ch & 3;                  // chunk 0..3
        int pc  = cc ^ ((row >> 1) & 3);   // swizzled chunk
        cp16(sA + row * 64 + pc * 16, Ag + (size_t)row * D_ + dk + cc * 4);
        cp16(sB + row * 64 + pc * 16, Bg + (size_t)row * (2 * D_) + dk + cc * 4);
    }
}

__global__ __launch_bounds__(256, 2) void gemm_score_mma(
    const float* __restrict__ ctx, const float* __restrict__ Wa,
    const float* __restrict__ Va)
{
    extern __shared__ char smem[];
    const uint32_t sbase = smem_u32(smem);
    const int tid  = threadIdx.x;
    const int w    = tid >> 5;
    const int lane = tid & 31;
    const int g    = lane >> 2;            // row within 8
    const int t    = lane & 3;             // col within 4
    const int warpM = (w >> 2) * 64;
    const int warpN = (w & 3) * 32;
    const int colBase = blockIdx.x * BN;
    const int rowBase = blockIdx.y * BM;
    const int b = rowBase >> 11;           // 2048 rows per batch

    float* ht_s = (float*)(smem + SM_HT);
    float* va_s = (float*)(smem + SM_VA);
    float* red  = (float*)(smem + SM_RED);
    if (tid < 128) ht_s[tid] = g_ht[b * D_ + colBase + tid];
    else           va_s[tid - 128] = Va[colBase + tid - 128];

    const float* Ag = ctx + (size_t)rowBase * D_;
    const float* Bg = Wa + (size_t)colBase * (2 * D_) + D_;   // s-half

    float c[4][4][4];
    #pragma unroll
    for (int i = 0; i < 4; i++)
        #pragma unroll
        for (int j = 0; j < 4; j++)
            #pragma unroll
            for (int r = 0; r < 4; r++) c[i][j][r] = 0.f;

    #pragma unroll
    for (int s = 0; s < NSTAGE - 1; s++) {
        load_tile(sbase + STG(s), sbase + STG(s) + STG_B, Ag, Bg, s * BK, tid);
        CP_COMMIT();
    }

    for (int it = 0; it < NITER; it++) {
        CP_WAIT2();
        __syncthreads();
        const int st = it & (NSTAGE - 1);
        const uint32_t* As = (const uint32_t*)(smem + STG(st));
        const uint32_t* Bs = (const uint32_t*)(smem + STG(st) + STG_B);

        #pragma unroll
        for (int k8 = 0; k8 < 2; k8++) {
            uint32_t a[4][4], bf[4][2];
            #pragma unroll
            for (int i = 0; i < 4; i++) {
                int r0 = warpM + i * 16 + g;
                a[i][0] = As[sw_word(r0,     2 * k8,     t)];
                a[i][1] = As[sw_word(r0 + 8, 2 * k8,     t)];
                a[i][2] = As[sw_word(r0,     2 * k8 + 1, t)];
                a[i][3] = As[sw_word(r0 + 8, 2 * k8 + 1, t)];
            }
            #pragma unroll
            for (int j = 0; j < 4; j++) {
                int r0 = warpN + j * 8 + g;
                bf[j][0] = Bs[sw_word(r0, 2 * k8,     t)];
                bf[j][1] = Bs[sw_word(r0, 2 * k8 + 1, t)];
            }
            #pragma unroll
            for (int i = 0; i < 4; i++)
                #pragma unroll
                for (int j = 0; j < 4; j++)
                    mma_tf32(c[i][j], a[i], bf[j]);
        }
        if (it + NSTAGE - 1 < NITER) {
            const int ls = (it + NSTAGE - 1) & (NSTAGE - 1);
            load_tile(sbase + STG(ls), sbase + STG(ls) + STG_B,
                      Ag, Bg, (it + NSTAGE - 1) * BK, tid);
        }
        CP_COMMIT();
    }

    // Epilogue: tanh(c + ht) * Va, reduce over this block's 128 cols
    #pragma unroll
    for (int i = 0; i < 4; i++) {
        float s0 = 0.f, s1 = 0.f;
        #pragma unroll
        for (int j = 0; j < 4; j++) {
            int c0 = warpN + j * 8 + 2 * t;
            float h0 = ht_s[c0], h1 = ht_s[c0 + 1];
            float v0 = va_s[c0], v1 = va_s[c0 + 1];
            s0 += tanh_fma(c[i][j][0] + h0) * v0;
            s0 += tanh_fma(c[i][j][1] + h1) * v1;
            s1 += tanh_fma(c[i][j][2] + h0) * v0;
            s1 += tanh_fma(c[i][j][3] + h1) * v1;
        }
        s0 += __shfl_xor_sync(0xFFFFFFFFu, s0, 1);
        s0 += __shfl_xor_sync(0xFFFFFFFFu, s0, 2);
        s1 += __shfl_xor_sync(0xFFFFFFFFu, s1, 1);
        s1 += __shfl_xor_sync(0xFFFFFFFFu, s1, 2);
        if (t == 0) {
            red[(warpM + i * 16 + g) * 4 + (w & 3)] = s0;
            red[(warpM + i * 16 + 8 + g) * 4 + (w & 3)] = s1;
        }
    }
    __syncthreads();
    if (tid < 128) {
        float s = red[tid * 4] + red[tid * 4 + 1] + red[tid * 4 + 2] + red[tid * 4 + 3];
        g_spart[(size_t)(rowBase + tid) * NCB + blockIdx.x] = s;
    }
}

// ---------------------------------------------------------------------------
// softmax over L=2048 per batch
// ---------------------------------------------------------------------------
__global__ void softmax_kernel(float* __restrict__ out_attn) {
    int b   = blockIdx.x;
    int tid = threadIdx.x;      // 256
    __shared__ float sm[256];
    float local[8];
    float mx = -1e30f;
    #pragma unroll
    for (int i = 0; i < 8; i++) {
        int l = tid + i * 256;
        const float* p = g_spart + ((size_t)b * L_ + l) * NCB;
        float s = 0.f;
        #pragma unroll
        for (int q = 0; q < NCB; q++) s += p[q];
        local[i] = s;
        mx = fmaxf(mx, s);
    }
    sm[tid] = mx; __syncthreads();
    for (int o = 128; o; o >>= 1) {
        if (tid < o) sm[tid] = fmaxf(sm[tid], sm[tid + o]);
        __syncthreads();
    }
    mx = sm[0]; __syncthreads();
    float sum = 0.f;
    #pragma unroll
    for (int i = 0; i < 8; i++) { local[i] = expf(local[i] - mx); sum += local[i]; }
    sm[tid] = sum; __syncthreads();
    for (int o = 128; o; o >>= 1) {
        if (tid < o) sm[tid] += sm[tid + o];
        __syncthreads();
    }
    float inv = 1.f / sm[0];
    #pragma unroll
    for (int i = 0; i < 8; i++)
        out_attn[(size_t)b * L_ + tid + i * 256] = local[i] * inv;
}

// ---------------------------------------------------------------------------
// weighted[b,d] = sum_l attn[b,l] * ctx[b,l,d]   (256 threads, float4 lanes)
// ---------------------------------------------------------------------------
__global__ __launch_bounds__(256) void weighted_part_kernel(
    const float* __restrict__ ctx, const float* __restrict__ attn)
{
    int b  = blockIdx.y;
    int lc = blockIdx.x;            // 8 chunks of 256 l
    int t  = threadIdx.x;           // 256 float4 lanes (d = 4t..4t+3)
    __shared__ float sa[256];
    sa[t] = attn[(size_t)b * L_ + lc * 256 + t];
    __syncthreads();
    const float4* cb4 = (const float4*)(ctx + ((size_t)b * L_ + (size_t)lc * 256) * D_);
    float4 acc = make_float4(0.f, 0.f, 0.f, 0.f);
    #pragma unroll 4
    for (int l = 0; l < 256; l++) {
        float a = sa[l];
        float4 v = cb4[(size_t)l * 256 + t];
        acc.x = fmaf(a, v.x, acc.x);
        acc.y = fmaf(a, v.y, acc.y);
        acc.z = fmaf(a, v.z, acc.z);
        acc.w = fmaf(a, v.w, acc.w);
    }
    ((float4*)g_wpart)[((size_t)b * 8 + lc) * 256 + t] = acc;
}

__global__ void weighted_reduce_kernel(float* __restrict__ out_w) {
    int i = blockIdx.x * blockDim.x + threadIdx.x;
    if (i >= B_ * D_) return;
    int b = i >> 10, d = i & (D_ - 1);
    float s = 0.f;
    #pragma unroll
    for (int lc = 0; lc < 8; lc++)
        s += g_wpart[((size_t)b * 8 + lc) * D_ + d];
    out_w[i] = s;
}

// ---------------------------------------------------------------------------
extern "C" void kernel_launch(void* const* d_in, const int* in_sizes, int n_in,
                              void* d_out, int out_size) {
    const float* x   = (const float*)d_in[0];   // (32,1024)
    const float* ctx = (const float*)d_in[1];   // (32,2048,1024)
    const float* Wa  = (const float*)d_in[2];   // (1024,2048)
    const float* Va  = (const float*)d_in[3];   // (1,1024)
    float* out      = (float*)d_out;
    float* out_w    = out;                       // (32,1024)
    float* out_attn = out + B_ * D_;             // (32,2048)

    cudaFuncSetAttribute(gemm_score_mma,
                         cudaFuncAttributeMaxDynamicSharedMemorySize, SMEM_TOTAL);

    ht_kernel<<<(B_ * D_) / 8, 256>>>(x, Wa);
    gemm_score_mma<<<dim3(NCB, NRB), 256, SMEM_TOTAL>>>(ctx, Wa, Va);
    softmax_kernel<<<B_, 256>>>(out_attn);
    weighted_part_kernel<<<dim3(8, B_), 256>>>(ctx, out_attn);
    weighted_reduce_kernel<<<(B_ * D_ + 255) / 256, 256>>>(out_w);
}

// round 8
// speedup vs baseline: 5.6332x; 1.5802x over previous
#include <cuda_runtime.h>
#include <cuda_fp16.h>
#include <cstdint>
#include <math.h>

#define B_ 32
#define L_ 2048
#define D_ 1024

#define BM 128
#define BN 128
#define BK 32                    // halves per mainloop stage
#define NCB (D_ / BN)            // 8 col blocks (k-dim)
#define NRB ((B_ * L_) / BM)     // 512 row blocks
#define NITER (D_ / BK)          // 32 mainloop iterations
#define NSTAGE 4

// Scratch (no cudaMalloc allowed)
__device__ __half g_ctx_h[B_ * L_ * D_];     // 128 MB fp16 context
__device__ __half g_wa_h[D_ * D_];           // 2 MB fp16 Wa s-half (k-major)
__device__ float  g_ht[B_ * D_];             // 128 KB
__device__ float  g_spart[B_ * L_ * NCB];    // 2 MB
__device__ float  g_wpart[B_ * 32 * D_];     // 4 MB

// ---------------------------------------------------------------------------
__device__ __forceinline__ uint32_t smem_u32(const void* p) {
    uint32_t a;
    asm("{ .reg .u64 t; cvta.to.shared.u64 t, %1; cvt.u32.u64 %0, t; }"
        : "=r"(a) : "l"(p));
    return a;
}

__device__ __forceinline__ void cp16(uint32_t s, const void* g) {
    asm volatile("cp.async.cg.shared.global [%0], [%1], 16;"
                 :: "r"(s), "l"(g) : "memory");
}
#define CP_COMMIT() asm volatile("cp.async.commit_group;" ::: "memory")
#define CP_WAIT2()  asm volatile("cp.async.wait_group 2;" ::: "memory")

__device__ __forceinline__ void mma_f16(float* c, const uint32_t* a,
                                        const uint32_t* b) {
    asm volatile(
        "mma.sync.aligned.m16n8k16.row.col.f32.f16.f16.f32 "
        "{%0,%1,%2,%3}, {%4,%5,%6,%7}, {%8,%9}, {%0,%1,%2,%3};"
        : "+f"(c[0]), "+f"(c[1]), "+f"(c[2]), "+f"(c[3])
        : "r"(a[0]), "r"(a[1]), "r"(a[2]), "r"(a[3]), "r"(b[0]), "r"(b[1]));
}

// swizzled word index in a 128-row x 16-word (32-half, 64B) tile:
//   (row, chunk c 0..3, word t 0..3) -> row*16 + (c ^ ((row>>1)&3))*4 + t
__device__ __forceinline__ int sw_word(int row, int chunk, int t) {
    return row * 16 + ((chunk ^ ((row >> 1) & 3)) << 2) + t;
}

// FMA-only tanh (rational 13/6 + bit-hack Newton reciprocal). No MUFU.
__device__ __forceinline__ float tanh_fma(float x) {
    const float a1 = 4.89352455891786e-03f, a3 = 6.37261928875436e-04f,
                a5 = 1.48572235717979e-05f, a7 = 5.12229709037114e-08f,
                a9 = -8.60467152213735e-11f, a11 = 2.00018790482477e-13f,
                a13 = -2.76076847742355e-16f;
    const float b0 = 4.89352518554385e-03f, b2 = 2.26843463243900e-03f,
                b4 = 1.18534705686654e-04f, b6 = 1.19825839466702e-06f;
    x = fminf(fmaxf(x, -7.90531110763549805f), 7.90531110763549805f);
    float x2 = x * x;
    float p = fmaf(x2, a13, a11);
    p = fmaf(x2, p, a9);
    p = fmaf(x2, p, a7);
    p = fmaf(x2, p, a5);
    p = fmaf(x2, p, a3);
    p = fmaf(x2, p, a1);
    p = p * x;
    float q = fmaf(x2, b6, b4);
    q = fmaf(x2, q, b2);
    q = fmaf(x2, q, b0);
    float r = __int_as_float(0x7EF311C3 - __float_as_int(q));
    r = r * fmaf(-q, r, 2.0f);
    r = r * fmaf(-q, r, 2.0f);
    r = r * fmaf(-q, r, 2.0f);
    return p * r;
}

// ---------------------------------------------------------------------------
// convert ctx -> fp16 (8 elems/thread)
// ---------------------------------------------------------------------------
__global__ __launch_bounds__(256) void convert_ctx_kernel(const float* __restrict__ ctx) {
    size_t gid = (size_t)blockIdx.x * blockDim.x + threadIdx.x;
    const float4* in = (const float4*)ctx;
    float4 v0 = in[gid * 2];
    float4 v1 = in[gid * 2 + 1];
    __half2 h[4];
    h[0] = __floats2half2_rn(v0.x, v0.y);
    h[1] = __floats2half2_rn(v0.z, v0.w);
    h[2] = __floats2half2_rn(v1.x, v1.y);
    h[3] = __floats2half2_rn(v1.z, v1.w);
    ((uint4*)g_ctx_h)[gid] = *(uint4*)h;
}

// convert Wa s-half -> fp16 (k-major contiguous)
__global__ __launch_bounds__(256) void convert_wa_kernel(const float* __restrict__ Wa) {
    size_t gid = (size_t)blockIdx.x * blockDim.x + threadIdx.x;   // over 131072
    int k = (int)(gid >> 7);          // 0..1023
    int c = (int)(gid & 127);         // 8-elem chunk within row
    const float4* in = (const float4*)(Wa + (size_t)k * (2 * D_) + D_);
    float4 v0 = in[c * 2];
    float4 v1 = in[c * 2 + 1];
    __half2 h[4];
    h[0] = __floats2half2_rn(v0.x, v0.y);
    h[1] = __floats2half2_rn(v0.z, v0.w);
    h[2] = __floats2half2_rn(v1.x, v1.y);
    h[3] = __floats2half2_rn(v1.z, v1.w);
    ((uint4*)g_wa_h)[(size_t)k * 128 + c] = *(uint4*)h;
}

// ---------------------------------------------------------------------------
// ht_proj[b,k] = sum_d x[b,d] * Wa[k,d]  (t-half), full fp32
// ---------------------------------------------------------------------------
__global__ void ht_kernel(const float* __restrict__ x, const float* __restrict__ Wa) {
    int gw   = (blockIdx.x * blockDim.x + threadIdx.x) >> 5;
    int lane = threadIdx.x & 31;
    if (gw >= B_ * D_) return;
    int b = gw >> 10;
    int k = gw & (D_ - 1);
    const float* xr = x + (size_t)b * D_;
    const float* wr = Wa + (size_t)k * (2 * D_);
    float s = 0.f;
    #pragma unroll
    for (int d = lane * 4; d < D_; d += 32 * 4) {
        float4 xv = *(const float4*)(xr + d);
        float4 wv = *(const float4*)(wr + d);
        s += xv.x * wv.x + xv.y * wv.y + xv.z * wv.z + xv.w * wv.w;
    }
    #pragma unroll
    for (int o = 16; o; o >>= 1) s += __shfl_down_sync(0xFFFFFFFFu, s, o);
    if (lane == 0) g_ht[gw] = s;
}

// ---------------------------------------------------------------------------
// fp16 mma.sync fused GEMM + tanh + Va-dot
// smem: 4 stages x (A 8KB + B 8KB) = 65536
//   HT: 65536 (512), VA: 66048 (512), RED: 66560 (2048) -> 68608 total
// ---------------------------------------------------------------------------
#define STG(s)  ((s) * 16384)
#define STG_B   8192
#define SM_HT   65536
#define SM_VA   66048
#define SM_RED  66560
#define SMEM_TOTAL 68608

__device__ __forceinline__ void load_tile(uint32_t sA, uint32_t sB,
    const __half* __restrict__ Ag, const __half* __restrict__ Bg,
    int dk, int tid)
{
    #pragma unroll
    for (int i = 0; i < 2; i++) {
        int ch  = tid + i * 256;           // 0..511
        int row = ch >> 2;                 // 0..127
        int cc  = ch & 3;                  // 16B chunk (8 halves)
        int pc  = cc ^ ((row >> 1) & 3);   // swizzled chunk
        cp16(sA + row * 64 + pc * 16, Ag + (size_t)row * D_ + dk + cc * 8);
        cp16(sB + row * 64 + pc * 16, Bg + (size_t)row * D_ + dk + cc * 8);
    }
}

__global__ __launch_bounds__(256, 2) void gemm_score_mma(
    const float* __restrict__ Va)
{
    extern __shared__ char smem[];
    const uint32_t sbase = smem_u32(smem);
    const int tid  = threadIdx.x;
    const int w    = tid >> 5;
    const int lane = tid & 31;
    const int g    = lane >> 2;            // row within 8
    const int t    = lane & 3;             // word within 4
    const int warpM = (w >> 2) * 64;
    const int warpN = (w & 3) * 32;
    const int colBase = blockIdx.x * BN;
    const int rowBase = blockIdx.y * BM;
    const int b = rowBase >> 11;           // 2048 rows per batch

    float* ht_s = (float*)(smem + SM_HT);
    float* va_s = (float*)(smem + SM_VA);
    float* red  = (float*)(smem + SM_RED);
    if (tid < 128) ht_s[tid] = g_ht[b * D_ + colBase + tid];
    else           va_s[tid - 128] = Va[colBase + tid - 128];

    const __half* Ag = g_ctx_h + (size_t)rowBase * D_;
    const __half* Bg = g_wa_h + (size_t)colBase * D_;

    float c[4][4][4];
    #pragma unroll
    for (int i = 0; i < 4; i++)
        #pragma unroll
        for (int j = 0; j < 4; j++)
            #pragma unroll
            for (int r = 0; r < 4; r++) c[i][j][r] = 0.f;

    #pragma unroll
    for (int s = 0; s < NSTAGE - 1; s++) {
        load_tile(sbase + STG(s), sbase + STG(s) + STG_B, Ag, Bg, s * BK, tid);
        CP_COMMIT();
    }

    for (int it = 0; it < NITER; it++) {
        CP_WAIT2();
        __syncthreads();
        const int st = it & (NSTAGE - 1);
        const uint32_t* As = (const uint32_t*)(smem + STG(st));
        const uint32_t* Bs = (const uint32_t*)(smem + STG(st) + STG_B);

        #pragma unroll
        for (int s = 0; s < 2; s++) {              // two k16 steps
            uint32_t a[4][4], bf[4][2];
            #pragma unroll
            for (int i = 0; i < 4; i++) {
                int r0 = warpM + i * 16 + g;
                a[i][0] = As[sw_word(r0,     2 * s,     t)];
                a[i][1] = As[sw_word(r0 + 8, 2 * s,     t)];
                a[i][2] = As[sw_word(r0,     2 * s + 1, t)];
                a[i][3] = As[sw_word(r0 + 8, 2 * s + 1, t)];
            }
            #pragma unroll
            for (int j = 0; j < 4; j++) {
                int r0 = warpN + j * 8 + g;
                bf[j][0] = Bs[sw_word(r0, 2 * s,     t)];
                bf[j][1] = Bs[sw_word(r0, 2 * s + 1, t)];
            }
            #pragma unroll
            for (int i = 0; i < 4; i++)
                #pragma unroll
                for (int j = 0; j < 4; j++)
                    mma_f16(c[i][j], a[i], bf[j]);
        }
        if (it + NSTAGE - 1 < NITER) {
            const int ls = (it + NSTAGE - 1) & (NSTAGE - 1);
            load_tile(sbase + STG(ls), sbase + STG(ls) + STG_B,
                      Ag, Bg, (it + NSTAGE - 1) * BK, tid);
        }
        CP_COMMIT();
    }

    // Epilogue: tanh(c + ht) * Va, reduce over this block's 128 cols
    #pragma unroll
    for (int i = 0; i < 4; i++) {
        float s0 = 0.f, s1 = 0.f;
        #pragma unroll
        for (int j = 0; j < 4; j++) {
            int c0 = warpN + j * 8 + 2 * t;
            float h0 = ht_s[c0], h1 = ht_s[c0 + 1];
            float v0 = va_s[c0], v1 = va_s[c0 + 1];
            s0 += tanh_fma(c[i][j][0] + h0) * v0;
            s0 += tanh_fma(c[i][j][1] + h1) * v1;
            s1 += tanh_fma(c[i][j][2] + h0) * v0;
            s1 += tanh_fma(c[i][j][3] + h1) * v1;
        }
        s0 += __shfl_xor_sync(0xFFFFFFFFu, s0, 1);
        s0 += __shfl_xor_sync(0xFFFFFFFFu, s0, 2);
        s1 += __shfl_xor_sync(0xFFFFFFFFu, s1, 1);
        s1 += __shfl_xor_sync(0xFFFFFFFFu, s1, 2);
        if (t == 0) {
            red[(warpM + i * 16 + g) * 4 + (w & 3)] = s0;
            red[(warpM + i * 16 + 8 + g) * 4 + (w & 3)] = s1;
        }
    }
    __syncthreads();
    if (tid < 128) {
        float s = red[tid * 4] + red[tid * 4 + 1] + red[tid * 4 + 2] + red[tid * 4 + 3];
        g_spart[(size_t)(rowBase + tid) * NCB + blockIdx.x] = s;
    }
}

// ---------------------------------------------------------------------------
// softmax over L=2048 per batch
// ---------------------------------------------------------------------------
__global__ void softmax_kernel(float* __restrict__ out_attn) {
    int b   = blockIdx.x;
    int tid = threadIdx.x;      // 256
    __shared__ float sm[256];
    float local[8];
    float mx = -1e30f;
    #pragma unroll
    for (int i = 0; i < 8; i++) {
        int l = tid + i * 256;
        const float* p = g_spart + ((size_t)b * L_ + l) * NCB;
        float s = 0.f;
        #pragma unroll
        for (int q = 0; q < NCB; q++) s += p[q];
        local[i] = s;
        mx = fmaxf(mx, s);
    }
    sm[tid] = mx; __syncthreads();
    for (int o = 128; o; o >>= 1) {
        if (tid < o) sm[tid] = fmaxf(sm[tid], sm[tid + o]);
        __syncthreads();
    }
    mx = sm[0]; __syncthreads();
    float sum = 0.f;
    #pragma unroll
    for (int i = 0; i < 8; i++) { local[i] = expf(local[i] - mx); sum += local[i]; }
    sm[tid] = sum; __syncthreads();
    for (int o = 128; o; o >>= 1) {
        if (tid < o) sm[tid] += sm[tid + o];
        __syncthreads();
    }
    float inv = 1.f / sm[0];
    #pragma unroll
    for (int i = 0; i < 8; i++)
        out_attn[(size_t)b * L_ + tid + i * 256] = local[i] * inv;
}

// ---------------------------------------------------------------------------
// weighted[b,d] = sum_l attn[b,l] * ctx_h[b,l,d]   (fp16 ctx, 64 l per block)
// block: 128 threads, thread t -> d = 8t..8t+7; grid (32, B)
// ---------------------------------------------------------------------------
__global__ __launch_bounds__(128) void weighted_part_kernel(
    const float* __restrict__ attn)
{
    int b  = blockIdx.y;
    int lq = blockIdx.x;            // 32 chunks of 64 l
    int t  = threadIdx.x;           // 128 lanes of 8 halves
    __shared__ float sa[64];
    if (t < 64) sa[t] = attn[(size_t)b * L_ + lq * 64 + t];
    __syncthreads();
    const uint4* cb = (const uint4*)(g_ctx_h + ((size_t)b * L_ + (size_t)lq * 64) * D_);
    float acc[8];
    #pragma unroll
    for (int i = 0; i < 8; i++) acc[i] = 0.f;
    #pragma unroll 4
    for (int l = 0; l < 64; l++) {
        float a = sa[l];
        uint4 raw = cb[(size_t)l * 128 + t];
        const __half2* h2 = (const __half2*)&raw;
        #pragma unroll
        for (int q = 0; q < 4; q++) {
            float2 f = __half22float2(h2[q]);
            acc[2 * q]     = fmaf(a, f.x, acc[2 * q]);
            acc[2 * q + 1] = fmaf(a, f.y, acc[2 * q + 1]);
        }
    }
    float* dst = g_wpart + ((size_t)b * 32 + lq) * D_ + t * 8;
    *(float4*)dst       = *(float4*)&acc[0];
    *(float4*)(dst + 4) = *(float4*)&acc[4];
}

__global__ void weighted_reduce_kernel(float* __restrict__ out_w) {
    int i = blockIdx.x * blockDim.x + threadIdx.x;
    if (i >= B_ * D_) return;
    int b = i >> 10, d = i & (D_ - 1);
    float s = 0.f;
    #pragma unroll
    for (int lc = 0; lc < 32; lc++)
        s += g_wpart[((size_t)b * 32 + lc) * D_ + d];
    out_w[i] = s;
}

// ---------------------------------------------------------------------------
extern "C" void kernel_launch(void* const* d_in, const int* in_sizes, int n_in,
                              void* d_out, int out_size) {
    const float* x   = (const float*)d_in[0];   // (32,1024)
    const float* ctx = (const float*)d_in[1];   // (32,2048,1024)
    const float* Wa  = (const float*)d_in[2];   // (1024,2048)
    const float* Va  = (const float*)d_in[3];   // (1,1024)
    float* out      = (float*)d_out;
    float* out_w    = out;                       // (32,1024)
    float* out_attn = out + B_ * D_;             // (32,2048)

    cudaFuncSetAttribute(gemm_score_mma,
                         cudaFuncAttributeMaxDynamicSharedMemorySize, SMEM_TOTAL);

    convert_ctx_kernel<<<(B_ * L_ * D_ / 8) / 256, 256>>>(ctx);
    convert_wa_kernel<<<(D_ * D_ / 8) / 256, 256>>>(Wa);
    ht_kernel<<<(B_ * D_) / 8, 256>>>(x, Wa);
    gemm_score_mma<<<dim3(NCB, NRB), 256, SMEM_TOTAL>>>(Va);
    softmax_kernel<<<B_, 256>>>(out_attn);
    weighted_part_kernel<<<dim3(32, B_), 128>>>(out_attn);
    weighted_reduce_kernel<<<(B_ * D_ + 255) / 256, 256>>>(out_w);
}

// round 9
// speedup vs baseline: 6.2845x; 1.1156x over previous
#include <cuda_runtime.h>
#include <cuda_fp16.h>
#include <cstdint>
#include <math.h>

#define B_ 32
#define L_ 2048
#define D_ 1024

#define BM 128
#define BN 128
#define BK 32                    // halves per mainloop stage
#define NCB (D_ / BN)            // 8 col blocks (k-dim)
#define NRB ((B_ * L_) / BM)     // 512 row blocks
#define NITER (D_ / BK)          // 32 mainloop iterations
#define NSTAGE 4

// Scratch (no cudaMalloc allowed)
__device__ __half g_ctx_h[B_ * L_ * D_];     // 128 MB fp16 context
__device__ __half g_wa_h[D_ * D_];           // 2 MB fp16 Wa s-half (k-major)
__device__ float  g_ht[B_ * D_];             // 128 KB
__device__ float  g_spart[B_ * L_ * NCB];    // 2 MB
__device__ float  g_wpart[B_ * 32 * D_];     // 4 MB

// ---------------------------------------------------------------------------
__device__ __forceinline__ uint32_t smem_u32(const void* p) {
    uint32_t a;
    asm("{ .reg .u64 t; cvta.to.shared.u64 t, %1; cvt.u32.u64 %0, t; }"
        : "=r"(a) : "l"(p));
    return a;
}

__device__ __forceinline__ void cp16(uint32_t s, const void* g) {
    asm volatile("cp.async.cg.shared.global [%0], [%1], 16;"
                 :: "r"(s), "l"(g) : "memory");
}
#define CP_COMMIT() asm volatile("cp.async.commit_group;" ::: "memory")
#define CP_WAIT2()  asm volatile("cp.async.wait_group 2;" ::: "memory")

__device__ __forceinline__ void mma_f16(float* c, const uint32_t* a,
                                        const uint32_t* b) {
    asm volatile(
        "mma.sync.aligned.m16n8k16.row.col.f32.f16.f16.f32 "
        "{%0,%1,%2,%3}, {%4,%5,%6,%7}, {%8,%9}, {%0,%1,%2,%3};"
        : "+f"(c[0]), "+f"(c[1]), "+f"(c[2]), "+f"(c[3])
        : "r"(a[0]), "r"(a[1]), "r"(a[2]), "r"(a[3]), "r"(b[0]), "r"(b[1]));
}

__device__ __forceinline__ void ldsm_x4(uint32_t& r0, uint32_t& r1,
                                        uint32_t& r2, uint32_t& r3,
                                        uint32_t addr) {
    asm volatile("ldmatrix.sync.aligned.m8n8.x4.shared.b16 {%0,%1,%2,%3}, [%4];"
                 : "=r"(r0), "=r"(r1), "=r"(r2), "=r"(r3) : "r"(addr));
}

// FMA-only tanh (rational 13/6 + bit-hack Newton reciprocal). No MUFU.
__device__ __forceinline__ float tanh_fma(float x) {
    const float a1 = 4.89352455891786e-03f, a3 = 6.37261928875436e-04f,
                a5 = 1.48572235717979e-05f, a7 = 5.12229709037114e-08f,
                a9 = -8.60467152213735e-11f, a11 = 2.00018790482477e-13f,
                a13 = -2.76076847742355e-16f;
    const float b0 = 4.89352518554385e-03f, b2 = 2.26843463243900e-03f,
                b4 = 1.18534705686654e-04f, b6 = 1.19825839466702e-06f;
    x = fminf(fmaxf(x, -7.90531110763549805f), 7.90531110763549805f);
    float x2 = x * x;
    float p = fmaf(x2, a13, a11);
    p = fmaf(x2, p, a9);
    p = fmaf(x2, p, a7);
    p = fmaf(x2, p, a5);
    p = fmaf(x2, p, a3);
    p = fmaf(x2, p, a1);
    p = p * x;
    float q = fmaf(x2, b6, b4);
    q = fmaf(x2, q, b2);
    q = fmaf(x2, q, b0);
    float r = __int_as_float(0x7EF311C3 - __float_as_int(q));
    r = r * fmaf(-q, r, 2.0f);
    r = r * fmaf(-q, r, 2.0f);
    r = r * fmaf(-q, r, 2.0f);
    return p * r;
}

// ---------------------------------------------------------------------------
// convert ctx -> fp16 (8 elems/thread)
// ---------------------------------------------------------------------------
__global__ __launch_bounds__(256) void convert_ctx_kernel(const float* __restrict__ ctx) {
    size_t gid = (size_t)blockIdx.x * blockDim.x + threadIdx.x;
    const float4* in = (const float4*)ctx;
    float4 v0 = in[gid * 2];
    float4 v1 = in[gid * 2 + 1];
    __half2 h[4];
    h[0] = __floats2half2_rn(v0.x, v0.y);
    h[1] = __floats2half2_rn(v0.z, v0.w);
    h[2] = __floats2half2_rn(v1.x, v1.y);
    h[3] = __floats2half2_rn(v1.z, v1.w);
    ((uint4*)g_ctx_h)[gid] = *(uint4*)h;
}

// convert Wa s-half -> fp16 (k-major contiguous)
__global__ __launch_bounds__(256) void convert_wa_kernel(const float* __restrict__ Wa) {
    size_t gid = (size_t)blockIdx.x * blockDim.x + threadIdx.x;   // over 131072
    int k = (int)(gid >> 7);          // 0..1023
    int c = (int)(gid & 127);         // 8-elem chunk within row
    const float4* in = (const float4*)(Wa + (size_t)k * (2 * D_) + D_);
    float4 v0 = in[c * 2];
    float4 v1 = in[c * 2 + 1];
    __half2 h[4];
    h[0] = __floats2half2_rn(v0.x, v0.y);
    h[1] = __floats2half2_rn(v0.z, v0.w);
    h[2] = __floats2half2_rn(v1.x, v1.y);
    h[3] = __floats2half2_rn(v1.z, v1.w);
    ((uint4*)g_wa_h)[(size_t)k * 128 + c] = *(uint4*)h;
}

// ---------------------------------------------------------------------------
// ht_proj[b,k] = sum_d x[b,d] * Wa[k,d]  (t-half), full fp32
// ---------------------------------------------------------------------------
__global__ void ht_kernel(const float* __restrict__ x, const float* __restrict__ Wa) {
    int gw   = (blockIdx.x * blockDim.x + threadIdx.x) >> 5;
    int lane = threadIdx.x & 31;
    if (gw >= B_ * D_) return;
    int b = gw >> 10;
    int k = gw & (D_ - 1);
    const float* xr = x + (size_t)b * D_;
    const float* wr = Wa + (size_t)k * (2 * D_);
    float s = 0.f;
    #pragma unroll
    for (int d = lane * 4; d < D_; d += 32 * 4) {
        float4 xv = *(const float4*)(xr + d);
        float4 wv = *(const float4*)(wr + d);
        s += xv.x * wv.x + xv.y * wv.y + xv.z * wv.z + xv.w * wv.w;
    }
    #pragma unroll
    for (int o = 16; o; o >>= 1) s += __shfl_down_sync(0xFFFFFFFFu, s, o);
    if (lane == 0) g_ht[gw] = s;
}

// ---------------------------------------------------------------------------
// fp16 mma.sync fused GEMM + tanh + Va-dot, ldmatrix fragment loads
// smem: 4 stages x (A 8KB + B 8KB) = 65536
//   HT: 65536 (512), VA: 66048 (512), RED: 66560 (2048) -> 68608 total
// ---------------------------------------------------------------------------
#define STG(s)  ((s) * 16384)
#define STG_B   8192
#define SM_HT   65536
#define SM_VA   66048
#define SM_RED  66560
#define SMEM_TOTAL 68608

__device__ __forceinline__ void load_tile(uint32_t sA, uint32_t sB,
    const __half* __restrict__ Ag, const __half* __restrict__ Bg,
    int dk, int tid)
{
    #pragma unroll
    for (int i = 0; i < 2; i++) {
        int ch  = tid + i * 256;           // 0..511
        int row = ch >> 2;                 // 0..127
        int cc  = ch & 3;                  // 16B chunk (8 halves)
        int pc  = cc ^ ((row >> 1) & 3);   // swizzled chunk
        cp16(sA + row * 64 + pc * 16, Ag + (size_t)row * D_ + dk + cc * 8);
        cp16(sB + row * 64 + pc * 16, Bg + (size_t)row * D_ + dk + cc * 8);
    }
}

__global__ __launch_bounds__(256, 2) void gemm_score_mma(
    const float* __restrict__ Va)
{
    extern __shared__ char smem[];
    const uint32_t sbase = smem_u32(smem);
    const int tid  = threadIdx.x;
    const int w    = tid >> 5;
    const int lane = tid & 31;
    const int g    = lane >> 2;            // row within 8 (epilogue)
    const int t    = lane & 3;             // word within 4 (epilogue)
    const int warpM = (w >> 2) * 64;
    const int warpN = (w & 3) * 32;
    const int colBase = blockIdx.x * BN;
    const int rowBase = blockIdx.y * BM;
    const int b = rowBase >> 11;           // 2048 rows per batch

    float* ht_s = (float*)(smem + SM_HT);
    float* va_s = (float*)(smem + SM_VA);
    float* red  = (float*)(smem + SM_RED);
    if (tid < 128) ht_s[tid] = g_ht[b * D_ + colBase + tid];
    else           va_s[tid - 128] = Va[colBase + tid - 128];

    const __half* Ag = g_ctx_h + (size_t)rowBase * D_;
    const __half* Bg = g_wa_h + (size_t)colBase * D_;

    // ldmatrix per-lane base offsets (within a stage's A / B tile)
    const int q  = lane >> 3;              // matrix index within x4
    const int r8 = lane & 7;               // row within 8x8 matrix
    uint32_t aOff[4], bOff[2];
    #pragma unroll
    for (int i = 0; i < 4; i++) {
        int R  = warpM + i * 16 + ((q & 1) << 3) + r8;
        int sw = (R >> 1) & 3;
        aOff[i] = (uint32_t)(R * 64 + ((sw ^ (q >> 1)) << 4));
    }
    #pragma unroll
    for (int jp = 0; jp < 2; jp++) {
        int R  = warpN + ((2 * jp + (q >> 1)) << 3) + r8;
        int sw = (R >> 1) & 3;
        bOff[jp] = (uint32_t)(R * 64 + ((sw ^ (q & 1)) << 4));
    }

    float c[4][4][4];
    #pragma unroll
    for (int i = 0; i < 4; i++)
        #pragma unroll
        for (int j = 0; j < 4; j++)
            #pragma unroll
            for (int r = 0; r < 4; r++) c[i][j][r] = 0.f;

    #pragma unroll
    for (int s = 0; s < NSTAGE - 1; s++) {
        load_tile(sbase + STG(s), sbase + STG(s) + STG_B, Ag, Bg, s * BK, tid);
        CP_COMMIT();
    }

    for (int it = 0; it < NITER; it++) {
        CP_WAIT2();
        __syncthreads();
        const int st = it & (NSTAGE - 1);
        const uint32_t stA = sbase + STG(st);
        const uint32_t stB = stA + STG_B;

        #pragma unroll
        for (int s = 0; s < 2; s++) {              // two k16 steps
            uint32_t a[4][4], bf[4][2];
            #pragma unroll
            for (int i = 0; i < 4; i++)
                ldsm_x4(a[i][0], a[i][1], a[i][2], a[i][3],
                        stA + (aOff[i] ^ (s << 5)));
            #pragma unroll
            for (int jp = 0; jp < 2; jp++)
                ldsm_x4(bf[2 * jp][0], bf[2 * jp][1],
                        bf[2 * jp + 1][0], bf[2 * jp + 1][1],
                        stB + (bOff[jp] ^ (s << 5)));
            #pragma unroll
            for (int i = 0; i < 4; i++)
                #pragma unroll
                for (int j = 0; j < 4; j++)
                    mma_f16(c[i][j], a[i], bf[j]);
        }
        if (it + NSTAGE - 1 < NITER) {
            const int ls = (it + NSTAGE - 1) & (NSTAGE - 1);
            load_tile(sbase + STG(ls), sbase + STG(ls) + STG_B,
                      Ag, Bg, (it + NSTAGE - 1) * BK, tid);
        }
        CP_COMMIT();
    }

    // Epilogue: tanh(c + ht) * Va, reduce over this block's 128 cols
    #pragma unroll
    for (int i = 0; i < 4; i++) {
        float s0 = 0.f, s1 = 0.f;
        #pragma unroll
        for (int j = 0; j < 4; j++) {
            int c0 = warpN + j * 8 + 2 * t;
            float h0 = ht_s[c0], h1 = ht_s[c0 + 1];
            float v0 = va_s[c0], v1 = va_s[c0 + 1];
            s0 += tanh_fma(c[i][j][0] + h0) * v0;
            s0 += tanh_fma(c[i][j][1] + h1) * v1;
            s1 += tanh_fma(c[i][j][2] + h0) * v0;
            s1 += tanh_fma(c[i][j][3] + h1) * v1;
        }
        s0 += __shfl_xor_sync(0xFFFFFFFFu, s0, 1);
        s0 += __shfl_xor_sync(0xFFFFFFFFu, s0, 2);
        s1 += __shfl_xor_sync(0xFFFFFFFFu, s1, 1);
        s1 += __shfl_xor_sync(0xFFFFFFFFu, s1, 2);
        if (t == 0) {
            red[(warpM + i * 16 + g) * 4 + (w & 3)] = s0;
            red[(warpM + i * 16 + 8 + g) * 4 + (w & 3)] = s1;
        }
    }
    __syncthreads();
    if (tid < 128) {
        float s = red[tid * 4] + red[tid * 4 + 1] + red[tid * 4 + 2] + red[tid * 4 + 3];
        g_spart[(size_t)(rowBase + tid) * NCB + blockIdx.x] = s;
    }
}

// ---------------------------------------------------------------------------
// softmax over L=2048 per batch
// ---------------------------------------------------------------------------
__global__ void softmax_kernel(float* __restrict__ out_attn) {
    int b   = blockIdx.x;
    int tid = threadIdx.x;      // 256
    __shared__ float sm[256];
    float local[8];
    float mx = -1e30f;
    #pragma unroll
    for (int i = 0; i < 8; i++) {
        int l = tid + i * 256;
        const float* p = g_spart + ((size_t)b * L_ + l) * NCB;
        float s = 0.f;
        #pragma unroll
        for (int q = 0; q < NCB; q++) s += p[q];
        local[i] = s;
        mx = fmaxf(mx, s);
    }
    sm[tid] = mx; __syncthreads();
    for (int o = 128; o; o >>= 1) {
        if (tid < o) sm[tid] = fmaxf(sm[tid], sm[tid + o]);
        __syncthreads();
    }
    mx = sm[0]; __syncthreads();
    float sum = 0.f;
    #pragma unroll
    for (int i = 0; i < 8; i++) { local[i] = expf(local[i] - mx); sum += local[i]; }
    sm[tid] = sum; __syncthreads();
    for (int o = 128; o; o >>= 1) {
        if (tid < o) sm[tid] += sm[tid + o];
        __syncthreads();
    }
    float inv = 1.f / sm[0];
    #pragma unroll
    for (int i = 0; i < 8; i++)
        out_attn[(size_t)b * L_ + tid + i * 256] = local[i] * inv;
}

// ---------------------------------------------------------------------------
// weighted[b,d] = sum_l attn[b,l] * ctx_h[b,l,d]   (fp16 ctx, 64 l per block)
// ---------------------------------------------------------------------------
__global__ __launch_bounds__(128) void weighted_part_kernel(
    const float* __restrict__ attn)
{
    int b  = blockIdx.y;
    int lq = blockIdx.x;            // 32 chunks of 64 l
    int t  = threadIdx.x;           // 128 lanes of 8 halves
    __shared__ float sa[64];
    if (t < 64) sa[t] = attn[(size_t)b * L_ + lq * 64 + t];
    __syncthreads();
    const uint4* cb = (const uint4*)(g_ctx_h + ((size_t)b * L_ + (size_t)lq * 64) * D_);
    float acc[8];
    #pragma unroll
    for (int i = 0; i < 8; i++) acc[i] = 0.f;
    #pragma unroll 4
    for (int l = 0; l < 64; l++) {
        float a = sa[l];
        uint4 raw = cb[(size_t)l * 128 + t];
        const __half2* h2 = (const __half2*)&raw;
        #pragma unroll
        for (int q = 0; q < 4; q++) {
            float2 f = __half22float2(h2[q]);
            acc[2 * q]     = fmaf(a, f.x, acc[2 * q]);
            acc[2 * q + 1] = fmaf(a, f.y, acc[2 * q + 1]);
        }
    }
    float* dst = g_wpart + ((size_t)b * 32 + lq) * D_ + t * 8;
    *(float4*)dst       = *(float4*)&acc[0];
    *(float4*)(dst + 4) = *(float4*)&acc[4];
}

__global__ void weighted_reduce_kernel(float* __restrict__ out_w) {
    int i = blockIdx.x * blockDim.x + threadIdx.x;
    if (i >= B_ * D_) return;
    int b = i >> 10, d = i & (D_ - 1);
    float s = 0.f;
    #pragma unroll
    for (int lc = 0; lc < 32; lc++)
        s += g_wpart[((size_t)b * 32 + lc) * D_ + d];
    out_w[i] = s;
}

// ---------------------------------------------------------------------------
extern "C" void kernel_launch(void* const* d_in, const int* in_sizes, int n_in,
                              void* d_out, int out_size) {
    const float* x   = (const float*)d_in[0];   // (32,1024)
    const float* ctx = (const float*)d_in[1];   // (32,2048,1024)
    const float* Wa  = (const float*)d_in[2];   // (1024,2048)
    const float* Va  = (const float*)d_in[3];   // (1,1024)
    float* out      = (float*)d_out;
    float* out_w    = out;                       // (32,1024)
    float* out_attn = out + B_ * D_;             // (32,2048)

    cudaFuncSetAttribute(gemm_score_mma,
                         cudaFuncAttributeMaxDynamicSharedMemorySize, SMEM_TOTAL);

    convert_ctx_kernel<<<(B_ * L_ * D_ / 8) / 256, 256>>>(ctx);
    convert_wa_kernel<<<(D_ * D_ / 8) / 256, 256>>>(Wa);
    ht_kernel<<<(B_ * D_) / 8, 256>>>(x, Wa);
    gemm_score_mma<<<dim3(NCB, NRB), 256, SMEM_TOTAL>>>(Va);
    softmax_kernel<<<B_, 256>>>(out_attn);
    weighted_part_kernel<<<dim3(32, B_), 128>>>(out_attn);
    weighted_reduce_kernel<<<(B_ * D_ + 255) / 256, 256>>>(out_w);
}

// round 10
// speedup vs baseline: 6.6854x; 1.0638x over previous
#include <cuda_runtime.h>
#include <cuda_fp16.h>
#include <cstdint>
#include <math.h>

#define B_ 32
#define L_ 2048
#define D_ 1024

#define BM 128
#define BN 128
#define BK 64                    // halves per mainloop stage (128 B/row)
#define NCB (D_ / BN)            // 8 col blocks (k-dim)
#define NRB ((B_ * L_) / BM)     // 512 row blocks
#define NITER (D_ / BK)          // 16 mainloop iterations
#define NSTAGE 3

// Scratch (no cudaMalloc allowed)
__device__ __half g_ctx_h[B_ * L_ * D_];     // 128 MB fp16 context
__device__ __half g_wa_h[D_ * D_];           // 2 MB fp16 Wa s-half (k-major)
__device__ float  g_ht[B_ * D_];             // 128 KB
__device__ float  g_spart[B_ * L_ * NCB];    // 2 MB
__device__ float  g_wpart[B_ * 32 * D_];     // 4 MB

// ---------------------------------------------------------------------------
__device__ __forceinline__ uint32_t smem_u32(const void* p) {
    uint32_t a;
    asm("{ .reg .u64 t; cvta.to.shared.u64 t, %1; cvt.u32.u64 %0, t; }"
        : "=r"(a) : "l"(p));
    return a;
}

__device__ __forceinline__ void cp16(uint32_t s, const void* g) {
    asm volatile("cp.async.cg.shared.global [%0], [%1], 16;"
                 :: "r"(s), "l"(g) : "memory");
}
#define CP_COMMIT() asm volatile("cp.async.commit_group;" ::: "memory")
#define CP_WAIT1()  asm volatile("cp.async.wait_group 1;" ::: "memory")

__device__ __forceinline__ void mma_f16(float* c, const uint32_t* a,
                                        const uint32_t* b) {
    asm volatile(
        "mma.sync.aligned.m16n8k16.row.col.f32.f16.f16.f32 "
        "{%0,%1,%2,%3}, {%4,%5,%6,%7}, {%8,%9}, {%0,%1,%2,%3};"
        : "+f"(c[0]), "+f"(c[1]), "+f"(c[2]), "+f"(c[3])
        : "r"(a[0]), "r"(a[1]), "r"(a[2]), "r"(a[3]), "r"(b[0]), "r"(b[1]));
}

__device__ __forceinline__ void ldsm_x4(uint32_t& r0, uint32_t& r1,
                                        uint32_t& r2, uint32_t& r3,
                                        uint32_t addr) {
    asm volatile("ldmatrix.sync.aligned.m8n8.x4.shared.b16 {%0,%1,%2,%3}, [%4];"
                 : "=r"(r0), "=r"(r1), "=r"(r2), "=r"(r3) : "r"(addr));
}

// FMA-only tanh (rational 13/6 + bit-hack Newton reciprocal). No MUFU.
__device__ __forceinline__ float tanh_fma(float x) {
    const float a1 = 4.89352455891786e-03f, a3 = 6.37261928875436e-04f,
                a5 = 1.48572235717979e-05f, a7 = 5.12229709037114e-08f,
                a9 = -8.60467152213735e-11f, a11 = 2.00018790482477e-13f,
                a13 = -2.76076847742355e-16f;
    const float b0 = 4.89352518554385e-03f, b2 = 2.26843463243900e-03f,
                b4 = 1.18534705686654e-04f, b6 = 1.19825839466702e-06f;
    x = fminf(fmaxf(x, -7.90531110763549805f), 7.90531110763549805f);
    float x2 = x * x;
    float p = fmaf(x2, a13, a11);
    p = fmaf(x2, p, a9);
    p = fmaf(x2, p, a7);
    p = fmaf(x2, p, a5);
    p = fmaf(x2, p, a3);
    p = fmaf(x2, p, a1);
    p = p * x;
    float q = fmaf(x2, b6, b4);
    q = fmaf(x2, q, b2);
    q = fmaf(x2, q, b0);
    float r = __int_as_float(0x7EF311C3 - __float_as_int(q));
    r = r * fmaf(-q, r, 2.0f);
    r = r * fmaf(-q, r, 2.0f);
    r = r * fmaf(-q, r, 2.0f);
    return p * r;
}

// ---------------------------------------------------------------------------
// convert ctx -> fp16 (8 elems/thread)
// ---------------------------------------------------------------------------
__global__ __launch_bounds__(256) void convert_ctx_kernel(const float* __restrict__ ctx) {
    size_t gid = (size_t)blockIdx.x * blockDim.x + threadIdx.x;
    const float4* in = (const float4*)ctx;
    float4 v0 = in[gid * 2];
    float4 v1 = in[gid * 2 + 1];
    __half2 h[4];
    h[0] = __floats2half2_rn(v0.x, v0.y);
    h[1] = __floats2half2_rn(v0.z, v0.w);
    h[2] = __floats2half2_rn(v1.x, v1.y);
    h[3] = __floats2half2_rn(v1.z, v1.w);
    ((uint4*)g_ctx_h)[gid] = *(uint4*)h;
}

// convert Wa s-half -> fp16 (k-major contiguous)
__global__ __launch_bounds__(256) void convert_wa_kernel(const float* __restrict__ Wa) {
    size_t gid = (size_t)blockIdx.x * blockDim.x + threadIdx.x;   // over 131072
    int k = (int)(gid >> 7);          // 0..1023
    int c = (int)(gid & 127);         // 8-elem chunk within row
    const float4* in = (const float4*)(Wa + (size_t)k * (2 * D_) + D_);
    float4 v0 = in[c * 2];
    float4 v1 = in[c * 2 + 1];
    __half2 h[4];
    h[0] = __floats2half2_rn(v0.x, v0.y);
    h[1] = __floats2half2_rn(v0.z, v0.w);
    h[2] = __floats2half2_rn(v1.x, v1.y);
    h[3] = __floats2half2_rn(v1.z, v1.w);
    ((uint4*)g_wa_h)[(size_t)k * 128 + c] = *(uint4*)h;
}

// ---------------------------------------------------------------------------
// ht_proj[b,k] = sum_d x[b,d] * Wa[k,d]  (t-half), full fp32
// ---------------------------------------------------------------------------
__global__ void ht_kernel(const float* __restrict__ x, const float* __restrict__ Wa) {
    int gw   = (blockIdx.x * blockDim.x + threadIdx.x) >> 5;
    int lane = threadIdx.x & 31;
    if (gw >= B_ * D_) return;
    int b = gw >> 10;
    int k = gw & (D_ - 1);
    const float* xr = x + (size_t)b * D_;
    const float* wr = Wa + (size_t)k * (2 * D_);
    float s = 0.f;
    #pragma unroll
    for (int d = lane * 4; d < D_; d += 32 * 4) {
        float4 xv = *(const float4*)(xr + d);
        float4 wv = *(const float4*)(wr + d);
        s += xv.x * wv.x + xv.y * wv.y + xv.z * wv.z + xv.w * wv.w;
    }
    #pragma unroll
    for (int o = 16; o; o >>= 1) s += __shfl_down_sync(0xFFFFFFFFu, s, o);
    if (lane == 0) g_ht[gw] = s;
}

// ---------------------------------------------------------------------------
// fp16 mma.sync fused GEMM + tanh + Va-dot, ldmatrix, BK=64, 3 stages
// smem: 3 stages x (A 16KB + B 16KB) = 98304
//   HT: 98304 (512), VA: 98816 (512), RED: 99328 (2048) -> 101376 total
// ---------------------------------------------------------------------------
#define STG(s)  ((s) * 32768)
#define STG_B   16384
#define SM_HT   98304
#define SM_VA   98816
#define SM_RED  99328
#define SMEM_TOTAL 101376

__device__ __forceinline__ void load_tile(uint32_t sA, uint32_t sB,
    const __half* __restrict__ Ag, const __half* __restrict__ Bg,
    int dk, int tid)
{
    #pragma unroll
    for (int i = 0; i < 4; i++) {
        int ch  = tid + i * 256;           // 0..1023
        int row = ch >> 3;                 // 0..127
        int cc  = ch & 7;                  // 16B chunk (8 halves)
        int pc  = cc ^ (row & 7);          // swizzled chunk
        cp16(sA + row * 128 + pc * 16, Ag + (size_t)row * D_ + dk + cc * 8);
        cp16(sB + row * 128 + pc * 16, Bg + (size_t)row * D_ + dk + cc * 8);
    }
}

__global__ __launch_bounds__(256, 2) void gemm_score_mma(
    const float* __restrict__ Va)
{
    extern __shared__ char smem[];
    const uint32_t sbase = smem_u32(smem);
    const int tid  = threadIdx.x;
    const int w    = tid >> 5;
    const int lane = tid & 31;
    const int g    = lane >> 2;            // row within 8 (epilogue)
    const int t    = lane & 3;             // word within 4 (epilogue)
    const int warpM = (w >> 2) * 64;
    const int warpN = (w & 3) * 32;
    const int colBase = blockIdx.x * BN;
    const int rowBase = blockIdx.y * BM;
    const int b = rowBase >> 11;           // 2048 rows per batch

    float* ht_s = (float*)(smem + SM_HT);
    float* va_s = (float*)(smem + SM_VA);
    float* red  = (float*)(smem + SM_RED);
    if (tid < 128) ht_s[tid] = g_ht[b * D_ + colBase + tid];
    else           va_s[tid - 128] = Va[colBase + tid - 128];

    const __half* Ag = g_ctx_h + (size_t)rowBase * D_;
    const __half* Bg = g_wa_h + (size_t)colBase * D_;

    // ldmatrix per-lane base offsets (within a stage's A / B tile, k16 step 0)
    const int q  = lane >> 3;              // matrix index within x4
    const int r8 = lane & 7;               // row within 8x8 matrix
    uint32_t aOff[4], bOff[2];
    #pragma unroll
    for (int i = 0; i < 4; i++) {
        int R  = warpM + i * 16 + ((q & 1) << 3) + r8;
        aOff[i] = (uint32_t)(R * 128 + (((q >> 1) ^ (R & 7)) << 4));
    }
    #pragma unroll
    for (int jp = 0; jp < 2; jp++) {
        int R  = warpN + ((2 * jp + (q >> 1)) << 3) + r8;
        bOff[jp] = (uint32_t)(R * 128 + (((q & 1) ^ (R & 7)) << 4));
    }

    float c[4][4][4];
    #pragma unroll
    for (int i = 0; i < 4; i++)
        #pragma unroll
        for (int j = 0; j < 4; j++)
            #pragma unroll
            for (int r = 0; r < 4; r++) c[i][j][r] = 0.f;

    #pragma unroll
    for (int s = 0; s < NSTAGE - 1; s++) {
        load_tile(sbase + STG(s), sbase + STG(s) + STG_B, Ag, Bg, s * BK, tid);
        CP_COMMIT();
    }

    for (int it = 0; it < NITER; it++) {
        CP_WAIT1();
        __syncthreads();
        const int st = (it < 15) ? (it % 3) : (it % 3);   // it % NSTAGE
        const uint32_t stA = sbase + STG(st);
        const uint32_t stB = stA + STG_B;

        #pragma unroll
        for (int s = 0; s < 4; s++) {              // four k16 steps
            uint32_t a[4][4], bf[4][2];
            #pragma unroll
            for (int i = 0; i < 4; i++)
                ldsm_x4(a[i][0], a[i][1], a[i][2], a[i][3],
                        stA + (aOff[i] ^ (s << 5)));
            #pragma unroll
            for (int jp = 0; jp < 2; jp++)
                ldsm_x4(bf[2 * jp][0], bf[2 * jp][1],
                        bf[2 * jp + 1][0], bf[2 * jp + 1][1],
                        stB + (bOff[jp] ^ (s << 5)));
            #pragma unroll
            for (int i = 0; i < 4; i++)
                #pragma unroll
                for (int j = 0; j < 4; j++)
                    mma_f16(c[i][j], a[i], bf[j]);
        }
        if (it + NSTAGE - 1 < NITER) {
            const int ls = (it + NSTAGE - 1) % NSTAGE;
            load_tile(sbase + STG(ls), sbase + STG(ls) + STG_B,
                      Ag, Bg, (it + NSTAGE - 1) * BK, tid);
        }
        CP_COMMIT();
    }

    // Epilogue: tanh(c + ht) * Va, reduce over this block's 128 cols
    #pragma unroll
    for (int i = 0; i < 4; i++) {
        float s0 = 0.f, s1 = 0.f;
        #pragma unroll
        for (int j = 0; j < 4; j++) {
            int c0 = warpN + j * 8 + 2 * t;
            float h0 = ht_s[c0], h1 = ht_s[c0 + 1];
            float v0 = va_s[c0], v1 = va_s[c0 + 1];
            s0 += tanh_fma(c[i][j][0] + h0) * v0;
            s0 += tanh_fma(c[i][j][1] + h1) * v1;
            s1 += tanh_fma(c[i][j][2] + h0) * v0;
            s1 += tanh_fma(c[i][j][3] + h1) * v1;
        }
        s0 += __shfl_xor_sync(0xFFFFFFFFu, s0, 1);
        s0 += __shfl_xor_sync(0xFFFFFFFFu, s0, 2);
        s1 += __shfl_xor_sync(0xFFFFFFFFu, s1, 1);
        s1 += __shfl_xor_sync(0xFFFFFFFFu, s1, 2);
        if (t == 0) {
            red[(warpM + i * 16 + g) * 4 + (w & 3)] = s0;
            red[(warpM + i * 16 + 8 + g) * 4 + (w & 3)] = s1;
        }
    }
    __syncthreads();
    if (tid < 128) {
        float s = red[tid * 4] + red[tid * 4 + 1] + red[tid * 4 + 2] + red[tid * 4 + 3];
        g_spart[(size_t)(rowBase + tid) * NCB + blockIdx.x] = s;
    }
}

// ---------------------------------------------------------------------------
// softmax over L=2048 per batch
// ---------------------------------------------------------------------------
__global__ void softmax_kernel(float* __restrict__ out_attn) {
    int b   = blockIdx.x;
    int tid = threadIdx.x;      // 256
    __shared__ float sm[256];
    float local[8];
    float mx = -1e30f;
    #pragma unroll
    for (int i = 0; i < 8; i++) {
        int l = tid + i * 256;
        const float* p = g_spart + ((size_t)b * L_ + l) * NCB;
        float s = 0.f;
        #pragma unroll
        for (int q = 0; q < NCB; q++) s += p[q];
        local[i] = s;
        mx = fmaxf(mx, s);
    }
    sm[tid] = mx; __syncthreads();
    for (int o = 128; o; o >>= 1) {
        if (tid < o) sm[tid] = fmaxf(sm[tid], sm[tid + o]);
        __syncthreads();
    }
    mx = sm[0]; __syncthreads();
    float sum = 0.f;
    #pragma unroll
    for (int i = 0; i < 8; i++) { local[i] = expf(local[i] - mx); sum += local[i]; }
    sm[tid] = sum; __syncthreads();
    for (int o = 128; o; o >>= 1) {
        if (tid < o) sm[tid] += sm[tid + o];
        __syncthreads();
    }
    float inv = 1.f / sm[0];
    #pragma unroll
    for (int i = 0; i < 8; i++)
        out_attn[(size_t)b * L_ + tid + i * 256] = local[i] * inv;
}

// ---------------------------------------------------------------------------
// weighted[b,d] = sum_l attn[b,l] * ctx_h[b,l,d]   (fp16 ctx, 64 l per block)
// ---------------------------------------------------------------------------
__global__ __launch_bounds__(128) void weighted_part_kernel(
    const float* __restrict__ attn)
{
    int b  = blockIdx.y;
    int lq = blockIdx.x;            // 32 chunks of 64 l
    int t  = threadIdx.x;           // 128 lanes of 8 halves
    __shared__ float sa[64];
    if (t < 64) sa[t] = attn[(size_t)b * L_ + lq * 64 + t];
    __syncthreads();
    const uint4* cb = (const uint4*)(g_ctx_h + ((size_t)b * L_ + (size_t)lq * 64) * D_);
    float acc[8];
    #pragma unroll
    for (int i = 0; i < 8; i++) acc[i] = 0.f;
    #pragma unroll 4
    for (int l = 0; l < 64; l++) {
        float a = sa[l];
        uint4 raw = cb[(size_t)l * 128 + t];
        const __half2* h2 = (const __half2*)&raw;
        #pragma unroll
        for (int q = 0; q < 4; q++) {
            float2 f = __half22float2(h2[q]);
            acc[2 * q]     = fmaf(a, f.x, acc[2 * q]);
            acc[2 * q + 1] = fmaf(a, f.y, acc[2 * q + 1]);
        }
    }
    float* dst = g_wpart + ((size_t)b * 32 + lq) * D_ + t * 8;
    *(float4*)dst       = *(float4*)&acc[0];
    *(float4*)(dst + 4) = *(float4*)&acc[4];
}

__global__ void weighted_reduce_kernel(float* __restrict__ out_w) {
    int i = blockIdx.x * blockDim.x + threadIdx.x;
    if (i >= B_ * D_) return;
    int b = i >> 10, d = i & (D_ - 1);
    float s = 0.f;
    #pragma unroll
    for (int lc = 0; lc < 32; lc++)
        s += g_wpart[((size_t)b * 32 + lc) * D_ + d];
    out_w[i] = s;
}

// ---------------------------------------------------------------------------
extern "C" void kernel_launch(void* const* d_in, const int* in_sizes, int n_in,
                              void* d_out, int out_size) {
    const float* x   = (const float*)d_in[0];   // (32,1024)
    const float* ctx = (const float*)d_in[1];   // (32,2048,1024)
    const float* Wa  = (const float*)d_in[2];   // (1024,2048)
    const float* Va  = (const float*)d_in[3];   // (1,1024)
    float* out      = (float*)d_out;
    float* out_w    = out;                       // (32,1024)
    float* out_attn = out + B_ * D_;             // (32,2048)

    cudaFuncSetAttribute(gemm_score_mma,
                         cudaFuncAttributeMaxDynamicSharedMemorySize, SMEM_TOTAL);

    convert_ctx_kernel<<<(B_ * L_ * D_ / 8) / 256, 256>>>(ctx);
    convert_wa_kernel<<<(D_ * D_ / 8) / 256, 256>>>(Wa);
    ht_kernel<<<(B_ * D_) / 8, 256>>>(x, Wa);
    gemm_score_mma<<<dim3(NCB, NRB), 256, SMEM_TOTAL>>>(Va);
    softmax_kernel<<<B_, 256>>>(out_attn);
    weighted_part_kernel<<<dim3(32, B_), 128>>>(out_attn);
    weighted_reduce_kernel<<<(B_ * D_ + 255) / 256, 256>>>(out_w);
}